// round 1
// baseline (speedup 1.0000x reference)
#include <cuda_runtime.h>
#include <math.h>
#include <float.h>

#define BB   2
#define NP   16384
#define FF   32
#define MM   4096
#define KK   64
#define HH   64
#define CO   128
#define NTOT (BB*NP)
#define MTOT (BB*MM)
#define CANDMAX 2048

static __device__ float g_pc[MTOT*3];
static __device__ float g_u[NTOT*HH];
static __device__ int   g_nbr[MTOT*KK];
static __device__ int   g_cnt[MTOT];

// ---------- packed f32x2 helpers (lane-wise identical rounding to scalar fp32) ----------
__device__ __forceinline__ unsigned long long pack2(float lo, float hi) {
    unsigned long long r;
    asm("mov.b64 %0, {%1, %2};" : "=l"(r) : "r"(__float_as_uint(lo)), "r"(__float_as_uint(hi)));
    return r;
}
__device__ __forceinline__ void unpack2(unsigned long long v, float &lo, float &hi) {
    unsigned a, b;
    asm("mov.b64 {%0, %1}, %2;" : "=r"(a), "=r"(b) : "l"(v));
    lo = __uint_as_float(a); hi = __uint_as_float(b);
}
__device__ __forceinline__ unsigned long long add2(unsigned long long a, unsigned long long b) {
    unsigned long long r; asm("add.rn.f32x2 %0, %1, %2;" : "=l"(r) : "l"(a), "l"(b)); return r;
}
__device__ __forceinline__ unsigned long long mul2(unsigned long long a, unsigned long long b) {
    unsigned long long r; asm("mul.rn.f32x2 %0, %1, %2;" : "=l"(r) : "l"(a), "l"(b)); return r;
}
__device__ __forceinline__ unsigned long long fma2(unsigned long long a, unsigned long long b, unsigned long long c) {
    unsigned long long r; asm("fma.rn.f32x2 %0, %1, %2, %3;" : "=l"(r) : "l"(a), "l"(b), "l"(c)); return r;
}

// =====================================================================================
// Kernel 1: exact FPS. One 1024-thread CTA per cloud; pos in smem; d[16] in registers.
// Bit-exact vs reference: non-FMA fp32 distance (mul,mul,mul,add,add), argmax with
// first-index tie-break (packed key: d_bits<<32 | ~idx, 64-bit max).
// =====================================================================================
__global__ __launch_bounds__(1024, 1) void fps_kernel(const float* __restrict__ pos) {
    extern __shared__ float sh[];
    float* sx = sh;
    float* sy = sh + NP;
    float* sz = sh + 2*NP;
    __shared__ unsigned long long swarp[32];
    __shared__ unsigned long long swin;

    const int b = blockIdx.x, tid = threadIdx.x;
    const int lane = tid & 31, wid = tid >> 5;
    const float* p = pos + (size_t)b * NP * 3;

    for (int i = tid; i < NP; i += 1024) {
        sx[i] = p[3*i]; sy[i] = p[3*i+1]; sz[i] = p[3*i+2];
    }
    __syncthreads();

    const int PT = 16;
    const int j0 = tid * PT;
    float d[PT];
    const float x0 = sx[0], y0 = sy[0], z0 = sz[0];
#pragma unroll
    for (int k = 0; k < PT; ++k) {
        float dx = __fsub_rn(sx[j0+k], x0);
        float dy = __fsub_rn(sy[j0+k], y0);
        float dz = __fsub_rn(sz[j0+k], z0);
        d[k] = __fadd_rn(__fadd_rn(__fmul_rn(dx,dx), __fmul_rn(dy,dy)), __fmul_rn(dz,dz));
    }
    if (tid == 0) {
        g_pc[((size_t)b*MM + 0)*3 + 0] = x0;
        g_pc[((size_t)b*MM + 0)*3 + 1] = y0;
        g_pc[((size_t)b*MM + 0)*3 + 2] = z0;
    }

    for (int m = 1; m < MM; ++m) {
        // local argmax over 16 (ascending scan, strict > keeps smaller index on tie)
        float bd = d[0]; int bj = j0;
#pragma unroll
        for (int k = 1; k < PT; ++k) {
            if (d[k] > bd) { bd = d[k]; bj = j0 + k; }
        }
        unsigned long long key =
            ((unsigned long long)__float_as_uint(bd) << 32) | (unsigned)(~bj);
#pragma unroll
        for (int o = 16; o > 0; o >>= 1) {
            unsigned long long v = __shfl_down_sync(0xffffffffu, key, o);
            if (v > key) key = v;
        }
        if (lane == 0) swarp[wid] = key;
        __syncthreads();
        if (wid == 0) {
            unsigned long long k2 = swarp[lane];
#pragma unroll
            for (int o = 16; o > 0; o >>= 1) {
                unsigned long long v = __shfl_down_sync(0xffffffffu, k2, o);
                if (v > k2) k2 = v;
            }
            if (lane == 0) {
                swin = k2;
                int wj = (int)(~(unsigned)k2);
                g_pc[((size_t)b*MM + m)*3 + 0] = sx[wj];
                g_pc[((size_t)b*MM + m)*3 + 1] = sy[wj];
                g_pc[((size_t)b*MM + m)*3 + 2] = sz[wj];
            }
        }
        __syncthreads();
        const int wj = (int)(~(unsigned)swin);
        const float wx = sx[wj], wy = sy[wj], wz = sz[wj];
        const unsigned long long nwx = pack2(-wx, -wx);
        const unsigned long long nwy = pack2(-wy, -wy);
        const unsigned long long nwz = pack2(-wz, -wz);
        const float2* sx2 = (const float2*)(sx + j0);
        const float2* sy2 = (const float2*)(sy + j0);
        const float2* sz2 = (const float2*)(sz + j0);
#pragma unroll
        for (int k = 0; k < PT/2; ++k) {
            float2 vx = sx2[k], vy = sy2[k], vz = sz2[k];
            unsigned long long dx = add2(pack2(vx.x, vx.y), nwx);
            unsigned long long dy = add2(pack2(vy.x, vy.y), nwy);
            unsigned long long dz = add2(pack2(vz.x, vz.y), nwz);
            unsigned long long s  = add2(add2(mul2(dx,dx), mul2(dy,dy)), mul2(dz,dz));
            float c0, c1; unpack2(s, c0, c1);
            d[2*k]   = fminf(d[2*k],   c0);
            d[2*k+1] = fminf(d[2*k+1], c1);
        }
    }
}

// =====================================================================================
// Kernel 2: per-point layer-1 partials  u_j = x_j@W1[:32] + p_j@W1[32:35] + b1
// =====================================================================================
__global__ __launch_bounds__(256) void feat_kernel(const float* __restrict__ x,
                                                   const float* __restrict__ pos,
                                                   const float* __restrict__ W1,
                                                   const float* __restrict__ b1) {
    __shared__ float xs[4][FF];
    __shared__ float ps[4][3];
    const int j0 = blockIdx.x * 4;
    const int tid = threadIdx.x;
    if (tid < 128) xs[tid >> 5][tid & 31] = x[(size_t)(j0 + (tid >> 5))*FF + (tid & 31)];
    if (tid < 12)  ps[tid / 3][tid % 3]   = pos[(size_t)j0*3 + tid];
    __syncthreads();
    const int pt = tid >> 6, h = tid & 63;
    float acc = b1[h];
#pragma unroll
    for (int f = 0; f < FF; ++f) acc += xs[pt][f] * W1[f*HH + h];
    acc += ps[pt][0] * W1[32*HH + h];
    acc += ps[pt][1] * W1[33*HH + h];
    acc += ps[pt][2] * W1[34*HH + h];
    g_u[(size_t)(j0 + pt)*HH + h] = acc;
}

// =====================================================================================
// Kernel 3: ball query. One 256-thread CTA per centroid; compact in-radius candidates
// (expected ~550, buffer 2048), bitonic-sort packed (d2,idx) keys ascending, take K.
// Key ordering == top_k on -d2 with stable (smaller-index) tie-break.
// =====================================================================================
__global__ __launch_bounds__(256) void ballq_kernel(const float* __restrict__ pos) {
    const float R2 = (float)(0.2 * 0.2);   // double 0.04.. rounded to f32 (matches JAX)
    const int i = blockIdx.x;
    const int b = i / MM;
    __shared__ unsigned long long cand[CANDMAX];
    __shared__ int cnt;
    const int tid = threadIdx.x;
    if (tid == 0) cnt = 0;
    const float cx = g_pc[(size_t)i*3 + 0];
    const float cy = g_pc[(size_t)i*3 + 1];
    const float cz = g_pc[(size_t)i*3 + 2];
    __syncthreads();
    const float* p = pos + (size_t)b * NP * 3;
    for (int j = tid; j < NP; j += 256) {
        float dx = __fsub_rn(cx, p[3*j]);
        float dy = __fsub_rn(cy, p[3*j+1]);
        float dz = __fsub_rn(cz, p[3*j+2]);
        float d2 = __fadd_rn(__fadd_rn(__fmul_rn(dx,dx), __fmul_rn(dy,dy)), __fmul_rn(dz,dz));
        if (d2 <= R2) {
            int sl = atomicAdd(&cnt, 1);
            if (sl < CANDMAX)
                cand[sl] = ((unsigned long long)__float_as_uint(d2) << 32) | (unsigned)j;
        }
    }
    __syncthreads();
    const int c = min(cnt, CANDMAX);
    for (int t = tid; t < CANDMAX; t += 256)
        if (t >= c) cand[t] = ~0ull;
    // bitonic sort ascending over 2048 keys
    for (int k = 2; k <= CANDMAX; k <<= 1) {
        for (int s = k >> 1; s > 0; s >>= 1) {
            __syncthreads();
            for (int t = tid; t < CANDMAX; t += 256) {
                int pr = t ^ s;
                if (pr > t) {
                    unsigned long long a = cand[t], bv = cand[pr];
                    bool up = ((t & k) == 0);
                    if ((a > bv) == up) { cand[t] = bv; cand[pr] = a; }
                }
            }
        }
    }
    __syncthreads();
    const int v = min(c, KK);
    if (tid < KK) g_nbr[(size_t)i*KK + tid] = (tid < v) ? (int)(unsigned)cand[tid] : 0;
    if (tid == 0) g_cnt[i] = v;
}

// =====================================================================================
// Kernel 4: layer 2 + max aggregation. One 128-thread CTA per centroid; thread owns one
// output channel; W2 column register-resident (packed f32x2); 2 neighbors per sweep.
// h1 = relu(u_j - v_i), v_i = (pc/R)@W1[32:35]; out = max_j(h1@W2col) + b2.
// =====================================================================================
__device__ __forceinline__ float dot64(const float* __restrict__ h1,
                                       const unsigned long long* __restrict__ w2p) {
    const float2* hb = (const float2*)h1;
    unsigned long long a0 = 0ull, a1 = 0ull;
#pragma unroll
    for (int h2 = 0; h2 < HH/2; h2 += 2) {
        float2 p0 = hb[h2], p1 = hb[h2 + 1];
        a0 = fma2(pack2(p0.x, p0.y), w2p[h2],     a0);
        a1 = fma2(pack2(p1.x, p1.y), w2p[h2 + 1], a1);
    }
    float l0, u0, l1, u1;
    unpack2(a0, l0, u0); unpack2(a1, l1, u1);
    return (l0 + u0) + (l1 + u1);
}

__global__ __launch_bounds__(128) void mlp_kernel(const float* __restrict__ W1,
                                                  const float* __restrict__ W2,
                                                  const float* __restrict__ b2,
                                                  float* __restrict__ out) {
    const int i = blockIdx.x;
    const int b = i / MM;
    const int tid = threadIdx.x;
    __shared__ float v[HH];
    __shared__ float h1buf[2][HH];

    unsigned long long w2p[HH/2];
#pragma unroll
    for (int h = 0; h < HH/2; ++h)
        w2p[h] = pack2(W2[(size_t)(2*h)*CO + tid], W2[(size_t)(2*h + 1)*CO + tid]);

    if (tid < HH) {
        float icx = __fdiv_rn(g_pc[(size_t)i*3 + 0], 0.2f);
        float icy = __fdiv_rn(g_pc[(size_t)i*3 + 1], 0.2f);
        float icz = __fdiv_rn(g_pc[(size_t)i*3 + 2], 0.2f);
        v[tid] = icx*W1[32*HH + tid] + icy*W1[33*HH + tid] + icz*W1[34*HH + tid];
    }
    const int cnt = g_cnt[i];
    float mx = -FLT_MAX;
    __syncthreads();

    const int which = tid >> 6, h = tid & 63;
    for (int jj = 0; jj < cnt; jj += 2) {
        int idx = jj + which;
        if (idx < cnt) {
            int nb = g_nbr[(size_t)i*KK + idx];
            h1buf[which][h] = fmaxf(g_u[((size_t)b*NP + nb)*HH + h] - v[h], 0.0f);
        }
        __syncthreads();
        mx = fmaxf(mx, dot64(h1buf[0], w2p));
        if (jj + 1 < cnt) mx = fmaxf(mx, dot64(h1buf[1], w2p));
        __syncthreads();
    }
    float res = (cnt > 0) ? (mx + b2[tid]) : 0.0f;
    out[(size_t)i*CO + tid] = res;
}

// =====================================================================================
// Kernel 5: tail outputs (centroid positions + batch vector), layout-guarded by out_size
// =====================================================================================
__global__ void tail_kernel(float* __restrict__ out, int has_pc, int has_batch) {
    const int i = blockIdx.x * 256 + threadIdx.x;
    if (has_pc && i < MTOT*3) out[(size_t)MTOT*CO + i] = g_pc[i];
    if (has_batch && i < MTOT) out[(size_t)MTOT*CO + (size_t)MTOT*3 + i] = (float)(i / MM);
}

extern "C" void kernel_launch(void* const* d_in, const int* in_sizes, int n_in,
                              void* d_out, int out_size) {
    const float* x   = (const float*)d_in[0];
    const float* pos = (const float*)d_in[1];
    // d_in[2] = batch (implied by layout, unused)
    const float* W1  = (const float*)d_in[3];
    const float* b1  = (const float*)d_in[4];
    const float* W2  = (const float*)d_in[5];
    const float* b2  = (const float*)d_in[6];
    float* out = (float*)d_out;

    cudaFuncSetAttribute(fps_kernel, cudaFuncAttributeMaxDynamicSharedMemorySize, 3*NP*4);

    fps_kernel<<<BB, 1024, 3*NP*4>>>(pos);
    feat_kernel<<<NTOT/4, 256>>>(x, pos, W1, b1);
    ballq_kernel<<<MTOT, 256>>>(pos);
    mlp_kernel<<<MTOT, 128>>>(W1, W2, b2, out);

    int has_pc    = out_size >= MTOT*CO + MTOT*3;
    int has_batch = out_size >= MTOT*CO + MTOT*3 + MTOT;
    if (has_pc)
        tail_kernel<<<(MTOT*3 + 255)/256, 256>>>(out, has_pc, has_batch);
}

// round 2
// speedup vs baseline: 4.1876x; 4.1876x over previous
#include <cuda_runtime.h>
#include <math.h>
#include <float.h>

#define BB   2
#define NP   16384
#define FF   32
#define MM   4096
#define KK   64
#define HH   64
#define CO   128
#define NTOT (BB*NP)
#define MTOT (BB*MM)
#define CANDMAX 2048

#define GFPS  8                 // CTAs per cloud (one cluster)
#define TFPS  256               // threads per FPS CTA
#define SHARD (NP/GFPS)         // 2048 points per CTA
#define PPT   (SHARD/TFPS)      // 8 points per thread

static __device__ float g_pc[MTOT*3];
static __device__ float g_u[NTOT*HH];
static __device__ int   g_nbr[MTOT*KK];
static __device__ int   g_cnt[MTOT];

// ---------- packed f32x2 helpers (lane-wise identical rounding to scalar fp32) ----------
__device__ __forceinline__ unsigned long long pack2(float lo, float hi) {
    unsigned long long r;
    asm("mov.b64 %0, {%1, %2};" : "=l"(r) : "r"(__float_as_uint(lo)), "r"(__float_as_uint(hi)));
    return r;
}
__device__ __forceinline__ void unpack2(unsigned long long v, float &lo, float &hi) {
    unsigned a, b;
    asm("mov.b64 {%0, %1}, %2;" : "=r"(a), "=r"(b) : "l"(v));
    lo = __uint_as_float(a); hi = __uint_as_float(b);
}
__device__ __forceinline__ unsigned long long fma2(unsigned long long a, unsigned long long b, unsigned long long c) {
    unsigned long long r; asm("fma.rn.f32x2 %0, %1, %2, %3;" : "=l"(r) : "l"(a), "l"(b), "l"(c)); return r;
}

// ---------- cluster helpers ----------
__device__ __forceinline__ unsigned cta_rank() {
    unsigned r; asm("mov.u32 %0, %%cluster_ctarank;" : "=r"(r)); return r;
}
__device__ __forceinline__ void cluster_sync_all() {
    asm volatile("barrier.cluster.arrive.aligned;" ::: "memory");
    asm volatile("barrier.cluster.wait.aligned;" ::: "memory");
}
__device__ __forceinline__ void st_cluster_u64(unsigned local_smem_addr, unsigned target_rank,
                                               unsigned long long v) {
    unsigned raddr;
    asm volatile("mapa.shared::cluster.u32 %0, %1, %2;" : "=r"(raddr)
                 : "r"(local_smem_addr), "r"(target_rank));
    asm volatile("st.shared::cluster.u64 [%0], %1;" :: "r"(raddr), "l"(v) : "memory");
}

// =====================================================================================
// Kernel 1: exact FPS, 8-CTA cluster per cloud. Coords + d in registers; per-iteration
// cross-CTA candidate exchange through DSMEM slots (double-buffered) + cluster.sync.
// Bit-exact vs reference: non-FMA fp32 distances; argmax key = d_bits<<32 | ~global_idx
// (64-bit max == largest d, ties -> smallest index, matching jnp.argmax).
// =====================================================================================
__global__ __launch_bounds__(TFPS, 1) __cluster_dims__(GFPS, 1, 1)
void fps_kernel(const float* __restrict__ pos) {
    extern __shared__ float sh[];
    float* sx = sh;
    float* sy = sh + NP;
    float* sz = sh + 2*NP;
    __shared__ unsigned long long swarp[TFPS/32];
    __shared__ unsigned long long slot[2][GFPS];

    const int tid = threadIdx.x, lane = tid & 31, wid = tid >> 5;
    const unsigned rank = cta_rank();
    const int b = blockIdx.x / GFPS;
    const float* p = pos + (size_t)b * NP * 3;

    // stage full cloud coords (SoA) into smem — used for winner-coord broadcast lookups
    for (int i = tid; i < NP; i += TFPS) {
        sx[i] = p[3*i]; sy[i] = p[3*i+1]; sz[i] = p[3*i+2];
    }
    __syncthreads();

    // own shard: coords + running min-distance live in registers
    const int jbase = (int)rank * SHARD + tid;
    float mx[PPT], my[PPT], mz[PPT], d[PPT];
    const float x0 = sx[0], y0 = sy[0], z0 = sz[0];
#pragma unroll
    for (int k = 0; k < PPT; ++k) {
        int j = jbase + k*TFPS;
        mx[k] = sx[j]; my[k] = sy[j]; mz[k] = sz[j];
        float dx = __fsub_rn(mx[k], x0);
        float dy = __fsub_rn(my[k], y0);
        float dz = __fsub_rn(mz[k], z0);
        d[k] = __fadd_rn(__fadd_rn(__fmul_rn(dx,dx), __fmul_rn(dy,dy)), __fmul_rn(dz,dz));
    }
    if (rank == 0 && tid == 0) {
        g_pc[((size_t)b*MM + 0)*3 + 0] = x0;
        g_pc[((size_t)b*MM + 0)*3 + 1] = y0;
        g_pc[((size_t)b*MM + 0)*3 + 2] = z0;
    }

    const unsigned slot_base = (unsigned)__cvta_generic_to_shared(&slot[0][0]);

    for (int m = 1; m < MM; ++m) {
        const int buf = m & 1;
        // --- local argmax over PPT points (ascending k keeps smallest idx on tie via ~j) ---
        unsigned long long key =
            ((unsigned long long)__float_as_uint(d[0]) << 32) | (unsigned)(~jbase);
#pragma unroll
        for (int k = 1; k < PPT; ++k) {
            unsigned long long kk =
                ((unsigned long long)__float_as_uint(d[k]) << 32) | (unsigned)(~(jbase + k*TFPS));
            if (kk > key) key = kk;
        }
        // --- warp reduce ---
#pragma unroll
        for (int o = 16; o > 0; o >>= 1) {
            unsigned long long v = __shfl_down_sync(0xffffffffu, key, o);
            if (v > key) key = v;
        }
        if (lane == 0) swarp[wid] = key;
        __syncthreads();
        // --- CTA reduce (8 warps) + broadcast CTA candidate to all cluster CTAs ---
        if (wid == 0) {
            unsigned long long k2 = (lane < TFPS/32) ? swarp[lane] : 0ull;
#pragma unroll
            for (int o = 4; o > 0; o >>= 1) {
                unsigned long long v = __shfl_down_sync(0xffffffffu, k2, o);
                if (v > k2) k2 = v;
            }
            if (lane == 0) {
                unsigned laddr = slot_base + (unsigned)(buf*GFPS + rank) * 8u;
#pragma unroll
                for (unsigned g = 0; g < GFPS; ++g)
                    st_cluster_u64(laddr, g, k2);
            }
        }
        cluster_sync_all();
        // --- every thread picks the global winner (deterministic) ---
        unsigned long long w = slot[buf][0];
#pragma unroll
        for (int g = 1; g < GFPS; ++g) {
            unsigned long long v = slot[buf][g];
            if (v > w) w = v;
        }
        const int wj = (int)(~(unsigned)w);
        const float wx = sx[wj], wy = sy[wj], wz = sz[wj];
        if (rank == 0 && tid == 0) {
            g_pc[((size_t)b*MM + m)*3 + 0] = wx;
            g_pc[((size_t)b*MM + m)*3 + 1] = wy;
            g_pc[((size_t)b*MM + m)*3 + 2] = wz;
        }
        // --- register min-update (exact op sequence) ---
#pragma unroll
        for (int k = 0; k < PPT; ++k) {
            float dx = __fsub_rn(mx[k], wx);
            float dy = __fsub_rn(my[k], wy);
            float dz = __fsub_rn(mz[k], wz);
            float s  = __fadd_rn(__fadd_rn(__fmul_rn(dx,dx), __fmul_rn(dy,dy)), __fmul_rn(dz,dz));
            d[k] = fminf(d[k], s);
        }
    }
}

// =====================================================================================
// Kernel 2: per-point layer-1 partials  u_j = x_j@W1[:32] + p_j@W1[32:35] + b1
// =====================================================================================
__global__ __launch_bounds__(256) void feat_kernel(const float* __restrict__ x,
                                                   const float* __restrict__ pos,
                                                   const float* __restrict__ W1,
                                                   const float* __restrict__ b1) {
    __shared__ float xs[4][FF];
    __shared__ float ps[4][3];
    const int j0 = blockIdx.x * 4;
    const int tid = threadIdx.x;
    if (tid < 128) xs[tid >> 5][tid & 31] = x[(size_t)(j0 + (tid >> 5))*FF + (tid & 31)];
    if (tid < 12)  ps[tid / 3][tid % 3]   = pos[(size_t)j0*3 + tid];
    __syncthreads();
    const int pt = tid >> 6, h = tid & 63;
    float acc = b1[h];
#pragma unroll
    for (int f = 0; f < FF; ++f) acc += xs[pt][f] * W1[f*HH + h];
    acc += ps[pt][0] * W1[32*HH + h];
    acc += ps[pt][1] * W1[33*HH + h];
    acc += ps[pt][2] * W1[34*HH + h];
    g_u[(size_t)(j0 + pt)*HH + h] = acc;
}

// =====================================================================================
// Kernel 3: ball query. Compact in-radius candidates; if cnt<=K emit directly (set
// semantics — downstream max-agg is order-invariant); else bitonic-sort next_pow2(cnt)
// packed (d2,idx) keys and take K smallest. Tie-break identical to stable top_k.
// =====================================================================================
__global__ __launch_bounds__(256) void ballq_kernel(const float* __restrict__ pos) {
    const float R2 = (float)(0.2 * 0.2);
    const int i = blockIdx.x;
    const int b = i / MM;
    __shared__ unsigned long long cand[CANDMAX];
    __shared__ int cnt;
    const int tid = threadIdx.x;
    if (tid == 0) cnt = 0;
    const float cx = g_pc[(size_t)i*3 + 0];
    const float cy = g_pc[(size_t)i*3 + 1];
    const float cz = g_pc[(size_t)i*3 + 2];
    __syncthreads();
    const float* p = pos + (size_t)b * NP * 3;
    for (int j = tid; j < NP; j += 256) {
        float dx = __fsub_rn(cx, p[3*j]);
        float dy = __fsub_rn(cy, p[3*j+1]);
        float dz = __fsub_rn(cz, p[3*j+2]);
        float d2 = __fadd_rn(__fadd_rn(__fmul_rn(dx,dx), __fmul_rn(dy,dy)), __fmul_rn(dz,dz));
        if (d2 <= R2) {
            int sl = atomicAdd(&cnt, 1);
            if (sl < CANDMAX)
                cand[sl] = ((unsigned long long)__float_as_uint(d2) << 32) | (unsigned)j;
        }
    }
    __syncthreads();
    const int c = min(cnt, CANDMAX);
    if (c > KK) {
        int p2 = KK;
        while (p2 < c) p2 <<= 1;
        for (int t = tid; t < p2; t += 256)
            if (t >= c) cand[t] = ~0ull;
        for (int k = 2; k <= p2; k <<= 1) {
            for (int s = k >> 1; s > 0; s >>= 1) {
                __syncthreads();
                for (int t = tid; t < p2; t += 256) {
                    int pr = t ^ s;
                    if (pr > t) {
                        unsigned long long a = cand[t], bv = cand[pr];
                        bool up = ((t & k) == 0);
                        if ((a > bv) == up) { cand[t] = bv; cand[pr] = a; }
                    }
                }
            }
        }
        __syncthreads();
    }
    const int v = min(c, KK);
    if (tid < KK) g_nbr[(size_t)i*KK + tid] = (tid < v) ? (int)(unsigned)cand[tid] : 0;
    if (tid == 0) g_cnt[i] = v;
}

// =====================================================================================
// Kernel 4: layer 2 + max aggregation (unchanged from R1 — 291us, revisit later)
// =====================================================================================
__device__ __forceinline__ float dot64(const float* __restrict__ h1,
                                       const unsigned long long* __restrict__ w2p) {
    const float2* hb = (const float2*)h1;
    unsigned long long a0 = 0ull, a1 = 0ull;
#pragma unroll
    for (int h2 = 0; h2 < HH/2; h2 += 2) {
        float2 p0 = hb[h2], p1 = hb[h2 + 1];
        a0 = fma2(pack2(p0.x, p0.y), w2p[h2],     a0);
        a1 = fma2(pack2(p1.x, p1.y), w2p[h2 + 1], a1);
    }
    float l0, u0, l1, u1;
    unpack2(a0, l0, u0); unpack2(a1, l1, u1);
    return (l0 + u0) + (l1 + u1);
}

__global__ __launch_bounds__(128) void mlp_kernel(const float* __restrict__ W1,
                                                  const float* __restrict__ W2,
                                                  const float* __restrict__ b2,
                                                  float* __restrict__ out) {
    const int i = blockIdx.x;
    const int b = i / MM;
    const int tid = threadIdx.x;
    __shared__ float v[HH];
    __shared__ float h1buf[2][HH];

    unsigned long long w2p[HH/2];
#pragma unroll
    for (int h = 0; h < HH/2; ++h)
        w2p[h] = pack2(W2[(size_t)(2*h)*CO + tid], W2[(size_t)(2*h + 1)*CO + tid]);

    if (tid < HH) {
        float icx = __fdiv_rn(g_pc[(size_t)i*3 + 0], 0.2f);
        float icy = __fdiv_rn(g_pc[(size_t)i*3 + 1], 0.2f);
        float icz = __fdiv_rn(g_pc[(size_t)i*3 + 2], 0.2f);
        v[tid] = icx*W1[32*HH + tid] + icy*W1[33*HH + tid] + icz*W1[34*HH + tid];
    }
    const int cnt = g_cnt[i];
    float mx = -FLT_MAX;
    __syncthreads();

    const int which = tid >> 6, h = tid & 63;
    for (int jj = 0; jj < cnt; jj += 2) {
        int idx = jj + which;
        if (idx < cnt) {
            int nb = g_nbr[(size_t)i*KK + idx];
            h1buf[which][h] = fmaxf(g_u[((size_t)b*NP + nb)*HH + h] - v[h], 0.0f);
        }
        __syncthreads();
        mx = fmaxf(mx, dot64(h1buf[0], w2p));
        if (jj + 1 < cnt) mx = fmaxf(mx, dot64(h1buf[1], w2p));
        __syncthreads();
    }
    float res = (cnt > 0) ? (mx + b2[tid]) : 0.0f;
    out[(size_t)i*CO + tid] = res;
}

// =====================================================================================
// Kernel 5: tail outputs (centroid positions + batch vector)
// =====================================================================================
__global__ void tail_kernel(float* __restrict__ out, int has_pc, int has_batch) {
    const int i = blockIdx.x * 256 + threadIdx.x;
    if (has_pc && i < MTOT*3) out[(size_t)MTOT*CO + i] = g_pc[i];
    if (has_batch && i < MTOT) out[(size_t)MTOT*CO + (size_t)MTOT*3 + i] = (float)(i / MM);
}

extern "C" void kernel_launch(void* const* d_in, const int* in_sizes, int n_in,
                              void* d_out, int out_size) {
    const float* x   = (const float*)d_in[0];
    const float* pos = (const float*)d_in[1];
    const float* W1  = (const float*)d_in[3];
    const float* b1  = (const float*)d_in[4];
    const float* W2  = (const float*)d_in[5];
    const float* b2  = (const float*)d_in[6];
    float* out = (float*)d_out;

    cudaFuncSetAttribute(fps_kernel, cudaFuncAttributeMaxDynamicSharedMemorySize, 3*NP*4);

    fps_kernel<<<BB*GFPS, TFPS, 3*NP*4>>>(pos);
    feat_kernel<<<NTOT/4, 256>>>(x, pos, W1, b1);
    ballq_kernel<<<MTOT, 256>>>(pos);
    mlp_kernel<<<MTOT, 128>>>(W1, W2, b2, out);

    int has_pc    = out_size >= MTOT*CO + MTOT*3;
    int has_batch = out_size >= MTOT*CO + MTOT*3 + MTOT;
    if (has_pc)
        tail_kernel<<<(MTOT*3 + 255)/256, 256>>>(out, has_pc, has_batch);
}